// round 14
// baseline (speedup 1.0000x reference)
#include <cuda_runtime.h>
#include <cuda_bf16.h>
#include <mma.h>
#include <cstdint>

// InteractionArch via wmma/HMMA split-GEMM (R10-validated math):
// out[b] = concat(dense[b](128),
//                 triu(k=1) of Gram([dense[b]; sparse[b].reshape(26,128)]))
// B=16384, D=128, F=26, OUTW=479.
//
// hi = rn_bf16(x), lo = rn_bf16(x - hi); G = hi.hi^T + hi.lo^T + lo.hi^T
// (lo.lo ~2^-18 dropped) -> rel_err 4.5e-6.
//
// R13 = R12 compute (one warp = one sample, K-split staging, 6 CTAs/SM)
// + COALESCED epilogue. The old per-row triu scatter generated ~676 L1tex
// store wavefronts per sample (26 STG x ~26 sectors each) -- the hidden
// ~64us wall. Now: G sits in smem scratch; lane writes out[128+t] for
// t=32i+lane (11 coalesced STG.32), gathering Gs[f*36+g] via the closed-form
// t->(f,g) inverse. Dense passthrough likewise rewritten as coalesced
// LDG.32/STG.32 (rows are L1-hot after staging).

#define FF   26
#define OUTW 479

#define LDM   136                    // 64 hi + 64 lo + 8 pad bf16 (272 B/row)
#define XW_B  (32 * LDM * 2)         // 8704 B per-warp tile
#define G_LDM 36                     // f32 elems/row of G scratch (reuses X)
#define SM_TOTAL (4 * XW_B)          // 34816 B per CTA

using namespace nvcuda;

__global__ void __launch_bounds__(128)
interact_wmma(const float* __restrict__ dense,
              const float* __restrict__ sparse,
              float* __restrict__ out)
{
    extern __shared__ char smem[];

    const int tid  = threadIdx.x;
    const int wid  = tid >> 5;
    const int lane = tid & 31;
    const int s    = blockIdx.x * 4 + wid;      // sample id

    __nv_bfloat16* X  = reinterpret_cast<__nv_bfloat16*>(smem + wid * XW_B);
    float*         Gs = reinterpret_cast<float*>(smem + wid * XW_B);

    float* ob = out + (size_t)s * OUTW;
    const float* drow = dense + (size_t)s * 128;

    const int rh = lane >> 4;        // row within the staged pair (0/1)
    const int q  = lane & 15;        // float4 quad within the 64-dim half

    wmma::fragment<wmma::accumulator, 16, 16, 16, float> c00, c01, c11;
    wmma::fill_fragment(c00, 0.0f);
    wmma::fill_fragment(c01, 0.0f);
    wmma::fill_fragment(c11, 0.0f);

#pragma unroll
    for (int h = 0; h < 2; ++h) {
        // ---- Stage rows 0..27 (row 27 zero), two rows per iteration ----
#pragma unroll
        for (int i = 0; i < 14; ++i) {
            const int r = 2 * i + rh;
            float4 x = make_float4(0.f, 0.f, 0.f, 0.f);
            if (r < 27) {
                const float* src = (r == 0)
                    ? drow
                    : sparse + (size_t)s * (FF * 128) + (size_t)(r - 1) * 128;
                x = reinterpret_cast<const float4*>(src + h * 64)[q];
            }

            // hi = rn_bf16(x), packed pairwise (low half = first elem).
            __nv_bfloat162 h01 = __floats2bfloat162_rn(x.x, x.y);
            __nv_bfloat162 h23 = __floats2bfloat162_rn(x.z, x.w);
            const uint32_t hw01 = reinterpret_cast<uint32_t&>(h01);
            const uint32_t hw23 = reinterpret_cast<uint32_t&>(h23);

            // lo = rn_bf16(x - hi); x - hi exact in fp32.
            const float l0 = x.x - __uint_as_float(hw01 << 16);
            const float l1 = x.y - __uint_as_float(hw01 & 0xFFFF0000u);
            const float l2 = x.z - __uint_as_float(hw23 << 16);
            const float l3 = x.w - __uint_as_float(hw23 & 0xFFFF0000u);
            __nv_bfloat162 p01 = __floats2bfloat162_rn(l0, l1);
            __nv_bfloat162 p23 = __floats2bfloat162_rn(l2, l3);

            const uint64_t hi64 = ((uint64_t)hw23 << 32) | hw01;
            const uint64_t lo64 = ((uint64_t)reinterpret_cast<uint32_t&>(p23) << 32)
                                  | reinterpret_cast<uint32_t&>(p01);

            *reinterpret_cast<uint64_t*>(X + r * LDM +      4 * q) = hi64;
            *reinterpret_cast<uint64_t*>(X + r * LDM + 64 + 4 * q) = lo64;
        }
        // Zero rows 28..31 (cols 0..127 = 256 B/row; 16 lanes x 16 B).
#pragma unroll
        for (int z = 0; z < 2; ++z) {
            const int r = 28 + 2 * z + rh;
            reinterpret_cast<uint4*>(X + r * LDM)[q] = make_uint4(0, 0, 0, 0);
        }
        __syncwarp();

        // ---- 4 k-steps over this half's 64 dims ----
#pragma unroll
        for (int k = 0; k < 4; ++k) {
            wmma::fragment<wmma::matrix_a, 16, 16, 16, __nv_bfloat16, wmma::row_major> a0h, a0l, a1h, a1l;
            wmma::fragment<wmma::matrix_b, 16, 16, 16, __nv_bfloat16, wmma::col_major> b0h, b0l, b1h, b1l;

            wmma::load_matrix_sync(a0h, X +                 k * 16, LDM);
            wmma::load_matrix_sync(a0l, X +            64 + k * 16, LDM);
            wmma::load_matrix_sync(a1h, X + 16 * LDM +      k * 16, LDM);
            wmma::load_matrix_sync(a1l, X + 16 * LDM + 64 + k * 16, LDM);
            wmma::load_matrix_sync(b0h, X +                 k * 16, LDM);
            wmma::load_matrix_sync(b0l, X +            64 + k * 16, LDM);
            wmma::load_matrix_sync(b1h, X + 16 * LDM +      k * 16, LDM);
            wmma::load_matrix_sync(b1l, X + 16 * LDM + 64 + k * 16, LDM);

            wmma::mma_sync(c00, a0h, b0h, c00);
            wmma::mma_sync(c00, a0h, b0l, c00);
            wmma::mma_sync(c00, a0l, b0h, c00);

            wmma::mma_sync(c01, a0h, b1h, c01);
            wmma::mma_sync(c01, a0h, b1l, c01);
            wmma::mma_sync(c01, a0l, b1h, c01);

            wmma::mma_sync(c11, a1h, b1h, c11);
            wmma::mma_sync(c11, a1h, b1l, c11);
            wmma::mma_sync(c11, a1l, b1h, c11);
        }
        __syncwarp();   // half h reads done before half h+1 overwrites X
    }

    // ---- Dense passthrough: coalesced (rows L1-hot from staging) ----
#pragma unroll
    for (int c = 0; c < 4; ++c)
        ob[c * 32 + lane] = drow[c * 32 + lane];

    // ---- X dead: reuse region as 32x36 f32 G scratch ----
    wmma::store_matrix_sync(Gs,                   c00, G_LDM, wmma::mem_row_major);
    wmma::store_matrix_sync(Gs + 16,              c01, G_LDM, wmma::mem_row_major);
    wmma::store_matrix_sync(Gs + 16 * G_LDM + 16, c11, G_LDM, wmma::mem_row_major);
    __syncwarp();

    // ---- Coalesced triu emission: out[128+t], t = 32i + lane ----
    // t -> (f, g): base(f) = f*(53-f)/2; f = floor(26.5 - sqrt(702.25 - 2t)).
#pragma unroll
    for (int i = 0; i < 11; ++i) {
        const int t = i * 32 + lane;
        if (t < 351) {
            int f = (int)(26.5f - sqrtf(702.25f - 2.0f * (float)t));
            while ((f + 1) * (52 - f) / 2 <= t) ++f;   // base(f+1) <= t
            while (f * (53 - f) / 2 > t) --f;          // base(f)   >  t
            const int g = t - f * (53 - f) / 2 + f + 1;
            ob[128 + t] = Gs[f * G_LDM + g];
        }
    }
}

extern "C" void kernel_launch(void* const* d_in, const int* in_sizes, int n_in,
                              void* d_out, int out_size)
{
    const float* dense  = (const float*)d_in[0];
    const float* sparse = (const float*)d_in[1];
    float* out = (float*)d_out;

    cudaFuncSetAttribute(interact_wmma,
                         cudaFuncAttributeMaxDynamicSharedMemorySize, SM_TOTAL);

    // 16384 samples / 4 per CTA -> 4096 CTAs of 128 threads; 6 CTAs/SM.
    interact_wmma<<<4096, 128, SM_TOTAL>>>(dense, sparse, out);
}

// round 15
// speedup vs baseline: 1.1372x; 1.1372x over previous
#include <cuda_runtime.h>
#include <cuda_bf16.h>
#include <mma.h>
#include <cstdint>

// InteractionArch HYBRID: even blocks run the R4 SIMT f32x2 path (FMA/ALU/
// issue-bound), odd blocks the R12 wmma split-GEMM path (tensor/LDSM-bound),
// each on half the 16384 samples. Block-parity interleave -> every wave mixes
// both kinds per SM, filling each path's stall slots with the other's issue.
// out[b] = concat(dense[b](128),
//                 triu(k=1) of Gram([dense[b]; sparse[b].reshape(26,128)]))

#define FF   26
#define NV   27
#define OUTW 479

typedef unsigned long long ull;

// ============================ SIMT path (R4) ============================

__device__ __forceinline__ ull mul2(ull a, ull b)
{
    ull d;
    asm("mul.rn.f32x2 %0, %1, %2;" : "=l"(d) : "l"(a), "l"(b));
    return d;
}
__device__ __forceinline__ ull fma2(ull a, ull b, ull c)
{
    ull d;
    asm("fma.rn.f32x2 %0, %1, %2, %3;" : "=l"(d) : "l"(a), "l"(b), "l"(c));
    return d;
}
__device__ __forceinline__ float hadd2(ull a)
{
    unsigned lo, hi;
    asm("mov.b64 {%0, %1}, %2;" : "=r"(lo), "=r"(hi) : "l"(a));
    return __uint_as_float(lo) + __uint_as_float(hi);
}
__device__ __forceinline__ float dotp(const ulonglong2 a, const ulonglong2 b)
{
    ull t = mul2(a.x, b.x);
    t = fma2(a.y, b.y, t);
    return hadd2(t);
}

// 32-element halving butterfly; lane j ends with the full sum of element j.
__device__ __forceinline__ float bfly32(float (&p)[32], const int lane)
{
#pragma unroll
    for (int m = 16; m >= 1; m >>= 1) {
#pragma unroll
        for (int i = 0; i < m; ++i) {
            const bool up  = (lane & m) != 0;
            float send = up ? p[i] : p[i + m];
            float recv = __shfl_xor_sync(0xffffffffu, send, m);
            float keep = up ? p[i + m] : p[i];
            p[i] = keep + recv;
        }
    }
    return p[0];
}

__device__ __forceinline__ void simt_path(const int bk,
                                          const float* __restrict__ dense,
                                          const float* __restrict__ sparse,
                                          float* __restrict__ out)
{
    const int wid  = threadIdx.x >> 5;
    const int lane = threadIdx.x & 31;
    const int gw   = bk * 4 + wid;                       // sample in [0, 8192)

    const ulonglong2* d2 = reinterpret_cast<const ulonglong2*>(dense)  + gw * 32;
    const ulonglong2* s2 = reinterpret_cast<const ulonglong2*>(sparse) + gw * (FF * 32);

    ulonglong2 v[NV];
    v[0] = d2[lane];
#pragma unroll
    for (int f = 0; f < FF; ++f)
        v[f + 1] = s2[f * 32 + lane];

    float* ob = out + (size_t)gw * OUTW;

    {   // dense passthrough
        unsigned a, b, c, d;
        asm("mov.b64 {%0, %1}, %2;" : "=r"(a), "=r"(b) : "l"(v[0].x));
        asm("mov.b64 {%0, %1}, %2;" : "=r"(c), "=r"(d) : "l"(v[0].y));
        ob[lane * 4 + 0] = __uint_as_float(a);
        ob[lane * 4 + 1] = __uint_as_float(b);
        ob[lane * 4 + 2] = __uint_as_float(c);
        ob[lane * 4 + 3] = __uint_as_float(d);
    }

    float p[32];
    int slot  = 0;
    int obase = 128;

#pragma unroll
    for (int f = 0; f < NV; ++f) {
#pragma unroll
        for (int g = f + 1; g < NV; ++g) {
            p[slot] = dotp(v[f], v[g]);
            ++slot;
            if (slot == 32) {
                float r = bfly32(p, lane);
                ob[obase + lane] = r;
                obase += 32;
                slot = 0;
            }
        }
    }

    p[31] = 0.0f;   // tail: 351 = 10*32 + 31
    {
        float r = bfly32(p, lane);
        if (lane < 31)
            ob[obase + lane] = r;
    }
}

// ============================ wmma path (R12) ============================

#define LDM   136                    // 64 hi + 64 lo + 8 pad bf16 (272 B/row)
#define XW_B  (32 * LDM * 2)         // 8704 B per-warp tile
#define G_LDM 36
#define SM_TOTAL (4 * XW_B)          // 34816 B per CTA

using namespace nvcuda;

__device__ __forceinline__ void wmma_path(const int bk, char* smem,
                                          const float* __restrict__ dense,
                                          const float* __restrict__ sparse,
                                          float* __restrict__ out)
{
    const int wid  = threadIdx.x >> 5;
    const int lane = threadIdx.x & 31;
    const int s    = 8192 + bk * 4 + wid;                // sample in [8192, 16384)

    __nv_bfloat16* X  = reinterpret_cast<__nv_bfloat16*>(smem + wid * XW_B);
    float*         Gs = reinterpret_cast<float*>(smem + wid * XW_B);

    float* ob = out + (size_t)s * OUTW;
    const float* drow = dense + (size_t)s * 128;

    const int rh = lane >> 4;
    const int q  = lane & 15;

    wmma::fragment<wmma::accumulator, 16, 16, 16, float> c00, c01, c11;
    wmma::fill_fragment(c00, 0.0f);
    wmma::fill_fragment(c01, 0.0f);
    wmma::fill_fragment(c11, 0.0f);

#pragma unroll
    for (int h = 0; h < 2; ++h) {
#pragma unroll
        for (int i = 0; i < 14; ++i) {
            const int r = 2 * i + rh;
            float4 x = make_float4(0.f, 0.f, 0.f, 0.f);
            if (r < 27) {
                const float* src = (r == 0)
                    ? drow
                    : sparse + (size_t)s * (FF * 128) + (size_t)(r - 1) * 128;
                x = reinterpret_cast<const float4*>(src + h * 64)[q];
                if (r == 0) {   // dense passthrough for this half's dims
                    float* od = ob + h * 64 + 4 * q;
                    od[0] = x.x; od[1] = x.y; od[2] = x.z; od[3] = x.w;
                }
            }

            __nv_bfloat162 h01 = __floats2bfloat162_rn(x.x, x.y);
            __nv_bfloat162 h23 = __floats2bfloat162_rn(x.z, x.w);
            const uint32_t hw01 = reinterpret_cast<uint32_t&>(h01);
            const uint32_t hw23 = reinterpret_cast<uint32_t&>(h23);

            const float l0 = x.x - __uint_as_float(hw01 << 16);
            const float l1 = x.y - __uint_as_float(hw01 & 0xFFFF0000u);
            const float l2 = x.z - __uint_as_float(hw23 << 16);
            const float l3 = x.w - __uint_as_float(hw23 & 0xFFFF0000u);
            __nv_bfloat162 p01 = __floats2bfloat162_rn(l0, l1);
            __nv_bfloat162 p23 = __floats2bfloat162_rn(l2, l3);

            const uint64_t hi64 = ((uint64_t)hw23 << 32) | hw01;
            const uint64_t lo64 = ((uint64_t)reinterpret_cast<uint32_t&>(p23) << 32)
                                  | reinterpret_cast<uint32_t&>(p01);

            *reinterpret_cast<uint64_t*>(X + r * LDM +      4 * q) = hi64;
            *reinterpret_cast<uint64_t*>(X + r * LDM + 64 + 4 * q) = lo64;
        }
#pragma unroll
        for (int z = 0; z < 2; ++z) {
            const int r = 28 + 2 * z + rh;
            reinterpret_cast<uint4*>(X + r * LDM)[q] = make_uint4(0, 0, 0, 0);
        }
        __syncwarp();

#pragma unroll
        for (int k = 0; k < 4; ++k) {
            wmma::fragment<wmma::matrix_a, 16, 16, 16, __nv_bfloat16, wmma::row_major> a0h, a0l, a1h, a1l;
            wmma::fragment<wmma::matrix_b, 16, 16, 16, __nv_bfloat16, wmma::col_major> b0h, b0l, b1h, b1l;

            wmma::load_matrix_sync(a0h, X +                 k * 16, LDM);
            wmma::load_matrix_sync(a0l, X +            64 + k * 16, LDM);
            wmma::load_matrix_sync(a1h, X + 16 * LDM +      k * 16, LDM);
            wmma::load_matrix_sync(a1l, X + 16 * LDM + 64 + k * 16, LDM);
            wmma::load_matrix_sync(b0h, X +                 k * 16, LDM);
            wmma::load_matrix_sync(b0l, X +            64 + k * 16, LDM);
            wmma::load_matrix_sync(b1h, X + 16 * LDM +      k * 16, LDM);
            wmma::load_matrix_sync(b1l, X + 16 * LDM + 64 + k * 16, LDM);

            wmma::mma_sync(c00, a0h, b0h, c00);
            wmma::mma_sync(c00, a0h, b0l, c00);
            wmma::mma_sync(c00, a0l, b0h, c00);

            wmma::mma_sync(c01, a0h, b1h, c01);
            wmma::mma_sync(c01, a0h, b1l, c01);
            wmma::mma_sync(c01, a0l, b1h, c01);

            wmma::mma_sync(c11, a1h, b1h, c11);
            wmma::mma_sync(c11, a1h, b1l, c11);
            wmma::mma_sync(c11, a1l, b1h, c11);
        }
        __syncwarp();
    }

    wmma::store_matrix_sync(Gs,                   c00, G_LDM, wmma::mem_row_major);
    wmma::store_matrix_sync(Gs + 16,              c01, G_LDM, wmma::mem_row_major);
    wmma::store_matrix_sync(Gs + 16 * G_LDM + 16, c11, G_LDM, wmma::mem_row_major);
    __syncwarp();

    // Scatter triu: lane f emits (f, g) for g = f+1..26 (R12 epilogue; the
    // R13 "coalesced" variant regressed -- keep the proven one).
    const int f = lane;
    if (f < 26) {
        const int rb = 128 + f * 26 - (f * (f - 1)) / 2 - f - 1;
        for (int g = f + 1; g < 27; ++g)
            ob[rb + g] = Gs[f * G_LDM + g];
    }
}

// ============================ dispatcher ============================

__global__ void __launch_bounds__(128, 4)
interact_hybrid(const float* __restrict__ dense,
                const float* __restrict__ sparse,
                float* __restrict__ out)
{
    extern __shared__ char smem[];
    const int bk = blockIdx.x >> 1;
    if ((blockIdx.x & 1) == 0)
        simt_path(bk, dense, sparse, out);
    else
        wmma_path(bk, smem, dense, sparse, out);
}

extern "C" void kernel_launch(void* const* d_in, const int* in_sizes, int n_in,
                              void* d_out, int out_size)
{
    const float* dense  = (const float*)d_in[0];
    const float* sparse = (const float*)d_in[1];
    float* out = (float*)d_out;

    // 4096 blocks: even -> SIMT samples [0,8192), odd -> wmma [8192,16384).
    // 34816 B smem (< 48K default, no attribute needed); 4 blocks/SM.
    interact_hybrid<<<4096, 128, SM_TOTAL>>>(dense, sparse, out);
}